// round 11
// baseline (speedup 1.0000x reference)
#include <cuda_runtime.h>
#include <cuda_bf16.h>
#include <cstdint>
#include <float.h>

#define N_VEC    32768
#define DIMS     256
#define KCODES   1024
#define MARGIN   0.06f

// -------- device scratch ----------------------------------------------------
__device__ __align__(16) float          g_eT[KCODES * DIMS];    // fp32 codes [K][D]
// augmented bf16 codes [K][272]: col 256 = -||e||^2/2, col 257 = 4.0, rest 0
__device__ __align__(16) __nv_bfloat16  g_eaug[KCODES * 272];
__device__ float  g_enorm2[KCODES];
__device__ double g_loss;

// -------- common helpers ------------------------------------------------------
__device__ __forceinline__ uint32_t smem_u32(const void* p) {
    uint32_t a;
    asm("{ .reg .u64 t; cvta.to.shared.u64 t, %1; cvt.u32.u64 %0, t; }"
        : "=r"(a) : "l"(p));
    return a;
}
__device__ __forceinline__ unsigned pack_bf2(float a, float b) {
    __nv_bfloat162 h = __floats2bfloat162_rn(a, b);
    return *reinterpret_cast<unsigned*>(&h);
}
__device__ __forceinline__ bool better(float v, int k, float v2, int k2) {
    return (v < v2) || (v == v2 && k < k2);
}
__device__ __forceinline__ void merge_top2(float& v1, int& k1, float& v2, int& k2,
                                           float ov1, int ok1, float ov2, int ok2) {
    float m1v, m2v; int m1k, m2k;
    if (better(v1, k1, ov1, ok1)) {
        m1v = v1; m1k = k1;
        if (better(v2, k2, ov1, ok1)) { m2v = v2; m2k = k2; }
        else                          { m2v = ov1; m2k = ok1; }
    } else {
        m1v = ov1; m1k = ok1;
        if (better(ov2, ok2, v1, k1)) { m2v = ov2; m2k = ok2; }
        else                          { m2v = v1;  m2k = k1;  }
    }
    v1 = m1v; k1 = m1k; v2 = m2v; k2 = m2k;
}

// packed-key helpers: key = (float_bits(acc) & ~0x3FF) | (1023 - k)
// acc positive, larger acc == smaller distance; umax picks winner, ties -> smaller k
__device__ __forceinline__ int key_k(uint32_t key) { return 1023 - (int)(key & 0x3FFu); }
__device__ __forceinline__ float key_score(uint32_t key) {
    // score = -2*(acc - 4) = 8 - 2*acc   (quantized acc rounded down -> score up <=5e-4)
    return fmaf(-2.f, __uint_as_float(key & 0xFFFFFC00u), 8.f);
}
// merge two descending key pairs -> top2 keys
__device__ __forceinline__ void kmerge2(uint32_t& a1, uint32_t& a2,
                                        uint32_t b1, uint32_t b2) {
    uint32_t n1 = umax(a1, b1);
    uint32_t n2 = umax(umin(a1, b1), umax(a2, b2));
    a1 = n1; a2 = n2;
}

// reference-rounding-emulation tie vote (identical to the rel_err=0 round-2 code)
__device__ int vote_tie(const float* __restrict__ x, int v, int ka, int kb) {
    const float* xr = x + (size_t)v * DIMS;
    const float* ea = g_eT + (size_t)ka * DIMS;
    const float* eb = g_eT + (size_t)kb * DIMS;
    double sA = 0.0, sBa = 0.0, sBb = 0.0;
    for (int d = 0; d < DIMS; d++) {
        double xv = (double)xr[d];
        sA  += xv * xv;
        sBa += xv * (double)ea[d];
        sBb += xv * (double)eb[d];
    }
    float Ba = (float)sBa, Bb = (float)sBb;
    float Ca = g_enorm2[ka], Cb = g_enorm2[kb];
    int ab = __float_as_int((float)sA);
    int votes = 0;
#pragma unroll
    for (int jj = -2; jj <= 2; jj++) {
        int w = 3 - (jj < 0 ? -jj : jj);
        float Aj = __int_as_float(ab + jj);
        float da = __fadd_rn(__fsub_rn(Aj, __fmul_rn(2.f, Ba)), Ca);
        float db = __fadd_rn(__fsub_rn(Aj, __fmul_rn(2.f, Bb)), Cb);
        if (da <= db) votes += w;
    }
    return (votes >= 5) ? ka : kb;
}

__device__ __forceinline__ float exact_score(const float4* xr, int k, float enk) {
    const float4* er = (const float4*)(g_eT + (size_t)k * DIMS);
    float a0 = 0.f, a1 = 0.f, a2 = 0.f, a3 = 0.f;
#pragma unroll 8
    for (int d4 = 0; d4 < DIMS / 4; d4++) {
        float4 xv = __ldg(xr + d4), ev = __ldg(er + d4);
        a0 = fmaf(xv.x, ev.x, a0); a1 = fmaf(xv.y, ev.y, a1);
        a2 = fmaf(xv.z, ev.z, a2); a3 = fmaf(xv.w, ev.w, a3);
    }
    return fmaf(-2.f, (a0 + a1) + (a2 + a3), enk);
}

// -------- pre-kernels ---------------------------------------------------------
__global__ void transpose_e_kernel(const float* __restrict__ e) {
    __shared__ float tile[32][33];
    int k0 = blockIdx.x * 32, d0 = blockIdx.y * 32;
    int tx = threadIdx.x, ty = threadIdx.y;
#pragma unroll
    for (int i = ty; i < 32; i += 8)
        tile[i][tx] = e[(size_t)(d0 + i) * KCODES + k0 + tx];
    __syncthreads();
#pragma unroll
    for (int j = ty; j < 32; j += 8)
        g_eT[(size_t)(k0 + j) * DIMS + d0 + tx] = tile[tx][j];
}

__global__ void enorm_kernel() {
    int k = blockIdx.x * 8 + (threadIdx.x >> 5);
    int lane = threadIdx.x & 31;
    const float* row = g_eT + (size_t)k * DIMS;
    double s = 0.0;
#pragma unroll
    for (int j = 0; j < 8; j++) {
        double v = (double)row[lane + 32 * j];
        s += v * v;
    }
#pragma unroll
    for (int off = 16; off; off >>= 1)
        s += __shfl_xor_sync(0xffffffffu, s, off);
    if (lane == 0) g_enorm2[k] = (float)s;
    if (blockIdx.x == 0 && threadIdx.x == 0) g_loss = 0.0;
}

// build augmented bf16 codes: [K][272] = [bf16(e) | -||e||^2/2, 4.0, 0 x14]
__global__ void convert_aug_kernel() {
    int i = blockIdx.x * 256 + threadIdx.x;        // 1024 * 34 uint4
    if (i >= KCODES * 34) return;
    int row = i / 34, c = i % 34;
    uint4 d = make_uint4(0u, 0u, 0u, 0u);
    if (c < 32) {
        const float4* s = (const float4*)(g_eT + (size_t)row * DIMS) + c * 2;
        float4 f0 = s[0], f1 = s[1];
        d.x = pack_bf2(f0.x, f0.y); d.y = pack_bf2(f0.z, f0.w);
        d.z = pack_bf2(f1.x, f1.y); d.w = pack_bf2(f1.z, f1.w);
    } else if (c == 32) {
        d.x = pack_bf2(-0.5f * g_enorm2[row], 4.0f);
    }
    ((uint4*)g_eaug)[i] = d;
}

// ============================================================================
// HMMA main kernel — 2 CTAs/SM, 16 warps, augmented GEMM + packed-key top-3
// ============================================================================
#define HT        512
#define H_MBLK    128
#define H_NCH     32
#define H_NCHUNKS 32
#define H_KS      17                  // 16 data k-steps + 1 aug k-step
#define H_RSTRIDE 560                 // 272 bf16 = 544 B + 16 pad
#define G_ROWB    544
#define SMH_ENS   0                                // 4096 B (exact ||e||^2)
#define SMH_BIDX  4096                             // 512 B
#define SMH_A     4608                             // 128*560 = 71680
#define SMH_B     (SMH_A + 128 * H_RSTRIDE)        // 76288
#define H_BUFSZ   (32 * H_RSTRIDE)                 // 17920
#define SMH_TOTAL (SMH_B + 2 * H_BUFSZ)            // 112128

__device__ __forceinline__ void cp16(uint32_t dst, const void* src) {
    asm volatile("cp.async.cg.shared.global [%0], [%1], 16;"
                 :: "r"(dst), "l"(src) : "memory");
}
#define CP_COMMIT() asm volatile("cp.async.commit_group;" ::: "memory")
#define CP_WAIT1()  asm volatile("cp.async.wait_group 1;" ::: "memory")

__device__ __forceinline__ void ldsm4(uint32_t* r, uint32_t addr) {
    asm volatile("ldmatrix.sync.aligned.m8n8.x4.shared.b16 {%0,%1,%2,%3}, [%4];"
                 : "=r"(r[0]), "=r"(r[1]), "=r"(r[2]), "=r"(r[3]) : "r"(addr));
}
__device__ __forceinline__ void mma16816(float* c, const uint32_t* a,
                                         uint32_t b0, uint32_t b1) {
    asm volatile("mma.sync.aligned.m16n8k16.row.col.f32.bf16.bf16.f32 "
                 "{%0,%1,%2,%3}, {%4,%5,%6,%7}, {%8,%9}, {%0,%1,%2,%3};"
                 : "+f"(c[0]), "+f"(c[1]), "+f"(c[2]), "+f"(c[3])
                 : "r"(a[0]), "r"(a[1]), "r"(a[2]), "r"(a[3]), "r"(b0), "r"(b1));
}

__global__ void __launch_bounds__(HT, 2)
vq_hmma_kernel(const float* __restrict__ x, float* __restrict__ out) {
    extern __shared__ char smem[];
    uint32_t sb = smem_u32(smem);
    float*  ens  = (float*)(smem + SMH_ENS);
    int*    bidx = (int*)(smem + SMH_BIDX);
    uint2*  scr  = (uint2*)(smem + SMH_B);          // reused after mainloop
    float4* scr2 = (float4*)(smem + SMH_B + 2048);  // reused after mainloop
    int tid = threadIdx.x, w = tid >> 5, L = tid & 31;
    int wm = w >> 1, wn = w & 1;
    int m0 = blockIdx.x * H_MBLK;

    for (int i = tid; i < KCODES; i += HT) ens[i] = g_enorm2[i];

    // A tile: x fp32 -> bf16, stride-560 smem, plus aug cols [1,1,0..0]
    const float4* xs = (const float4*)x;
    for (int u = tid; u < 4096; u += HT) {
        int row = u >> 5, c = u & 31;
        size_t s4 = ((size_t)(m0 + row)) * 64 + c * 2;
        float4 f0 = __ldg(xs + s4), f1 = __ldg(xs + s4 + 1);
        uint4 d;
        d.x = pack_bf2(f0.x, f0.y); d.y = pack_bf2(f0.z, f0.w);
        d.z = pack_bf2(f1.x, f1.y); d.w = pack_bf2(f1.z, f1.w);
        *(uint4*)(smem + SMH_A + row * H_RSTRIDE + c * 16) = d;
    }
    for (int u = tid; u < 256; u += HT) {           // aug cols 256..271
        int row = u >> 1, h = u & 1;
        uint4 d = make_uint4(h ? 0u : pack_bf2(1.f, 1.f), 0u, 0u, 0u);
        *(uint4*)(smem + SMH_A + row * H_RSTRIDE + 512 + h * 16) = d;
    }
    // preload B chunk 0 (32 augmented rows, 34 uint4 each)
    {
        const char* ebase = (const char*)g_eaug;
        for (int u = tid; u < 1088; u += HT) {
            int row = u / 34, c = u % 34;
            cp16(sb + SMH_B + row * H_RSTRIDE + c * 16,
                 ebase + (size_t)row * G_ROWB + c * 16);
        }
        CP_COMMIT();
    }

    // lane-dependent ldmatrix address parts
    uint32_t a_lane = sb + SMH_A + (uint32_t)(wm * 16 + (L & 15)) * H_RSTRIDE
                    + (uint32_t)(L >> 4) * 16;
    uint32_t b_lane = (uint32_t)(wn * 16 + (L & 7) + ((L >> 4) << 3)) * H_RSTRIDE
                    + (uint32_t)((L >> 3) & 1) * 16;

    // packed-key top-3 (descending) for 2 rows: wm*16 + {0,8} + (L>>2)
    uint32_t m1[2] = {0u, 0u}, m2[2] = {0u, 0u}, m3[2] = {0u, 0u};

#define UPDP(ri, kk, vv) do {                                                   \
    uint32_t key_ = (__float_as_uint(vv) & 0xFFFFFC00u)                         \
                  | (uint32_t)(1023 - (kk));                                    \
    uint32_t hi_  = umax(m1[ri], key_);                                         \
    uint32_t lo_  = umin(m1[ri], key_); m1[ri] = hi_;                           \
    uint32_t hi2_ = umax(m2[ri], lo_);                                          \
    uint32_t lo2_ = umin(m2[ri], lo_); m2[ri] = hi2_;                           \
    m3[ri] = umax(m3[ri], lo2_);                                                \
} while (0)

    for (int i = 0; i < H_NCHUNKS; i++) {
        if (i + 1 < H_NCHUNKS) {
            const char* ebase = (const char*)g_eaug + (size_t)(i + 1) * H_NCH * G_ROWB;
            uint32_t bdst = sb + SMH_B + ((i + 1) & 1) * H_BUFSZ;
            for (int u = tid; u < 1088; u += HT) {
                int row = u / 34, c = u % 34;
                cp16(bdst + row * H_RSTRIDE + c * 16,
                     ebase + (size_t)row * G_ROWB + c * 16);
            }
        }
        CP_COMMIT();
        CP_WAIT1();
        __syncthreads();                       // chunk i visible; A on i==0

        uint32_t bbase = sb + SMH_B + (i & 1) * H_BUFSZ + b_lane;

        float acc[2][4];                       // acc = f.e - ||e||^2/2 + 4 > 0
#pragma unroll
        for (int ni = 0; ni < 2; ni++)
#pragma unroll
            for (int c = 0; c < 4; c++) acc[ni][c] = 0.f;

#pragma unroll 4
        for (int ks = 0; ks < H_KS; ks++) {
            uint32_t af[4], bf[4];
            ldsm4(af, a_lane + ks * 32);
            ldsm4(bf, bbase + ks * 32);
            mma16816(acc[0], af, bf[0], bf[1]);
            mma16816(acc[1], af, bf[2], bf[3]);
        }

        int kb = i * H_NCH + wn * 16 + (L & 3) * 2;
        UPDP(0, kb,     acc[0][0]); UPDP(0, kb + 1, acc[0][1]);
        UPDP(1, kb,     acc[0][2]); UPDP(1, kb + 1, acc[0][3]);
        UPDP(0, kb + 8, acc[1][0]); UPDP(0, kb + 9, acc[1][1]);
        UPDP(1, kb + 8, acc[1][2]); UPDP(1, kb + 9, acc[1][3]);
        __syncthreads();                       // readers done before buf reuse
    }
#undef UPDP

    // ---- decision: quad key-merge -> smem cross-half -> rescue -> vote ----
    // Step A: per-warp quad merge of top2 keys, publish per (row, half)
#pragma unroll
    for (int ri = 0; ri < 2; ri++) {
        uint32_t a1 = m1[ri], a2 = m2[ri];
#pragma unroll
        for (int off = 1; off <= 2; off <<= 1) {
            uint32_t b1 = __shfl_xor_sync(0xffffffffu, a1, off);
            uint32_t b2 = __shfl_xor_sync(0xffffffffu, a2, off);
            kmerge2(a1, a2, b1, b2);
        }
        if ((L & 3) == 0) {
            int gr = wm * 16 + ri * 8 + (L >> 2);
            scr[gr * 2 + wn] = make_uint2(a1, a2);
        }
    }
    __syncthreads();

    // Step C: global top2 per row; if margin-tight, exact rescore own top3
#pragma unroll 1
    for (int ri = 0; ri < 2; ri++) {
        int gr = wm * 16 + ri * 8 + (L >> 2);
        uint2 h0 = scr[gr * 2 + 0], h1 = scr[gr * 2 + 1];
        uint32_t g1 = h0.x, g2 = h0.y;
        kmerge2(g1, g2, h1.x, h1.y);
        float gv1 = key_score(g1), gv2 = key_score(g2);
        bool need = (gv2 - gv1 < MARGIN);
        float ev1 = FLT_MAX, ev2 = FLT_MAX;
        int   ek1 = 0x7fffffff, ek2 = 0x7fffffff;
        if (__any_sync(0xffffffffu, need)) {
            if (need) {
                float lim = gv1 + MARGIN;
                const float4* xr = (const float4*)(x + (size_t)(m0 + gr) * DIMS);
                uint32_t mk[3] = { m1[ri], m2[ri], m3[ri] };
#pragma unroll
                for (int c = 0; c < 3; c++) {
                    if (mk[c] != 0u && key_score(mk[c]) <= lim) {
                        int kc = key_k(mk[c]);
                        float s = exact_score(xr, kc, ens[kc]);
                        if (s < ev1 || (s == ev1 && kc < ek1)) {
                            ev2 = ev1; ek2 = ek1; ev1 = s; ek1 = kc;
                        } else if (s < ev2 || (s == ev2 && kc < ek2)) {
                            ev2 = s; ek2 = kc;
                        }
                    }
                }
            }
#pragma unroll
            for (int off = 1; off <= 2; off <<= 1) {
                float ov1 = __shfl_xor_sync(0xffffffffu, ev1, off);
                int   ok1 = __shfl_xor_sync(0xffffffffu, ek1, off);
                float ov2 = __shfl_xor_sync(0xffffffffu, ev2, off);
                int   ok2 = __shfl_xor_sync(0xffffffffu, ek2, off);
                merge_top2(ev1, ek1, ev2, ek2, ov1, ok1, ov2, ok2);
            }
        }
        if ((L & 3) == 0)
            scr2[gr * 2 + wn] = make_float4(ev1, __int_as_float(ek1),
                                            ev2, __int_as_float(ek2));
    }
    __syncthreads();

    // Step E: wn==0 warps finalize each row
    if (wn == 0) {
#pragma unroll 1
        for (int ri = 0; ri < 2; ri++) {
            int gr = wm * 16 + ri * 8 + (L >> 2);
            uint2 h0 = scr[gr * 2 + 0], h1 = scr[gr * 2 + 1];
            uint32_t g1 = h0.x, g2 = h0.y;
            kmerge2(g1, g2, h1.x, h1.y);
            int widx = key_k(g1);
            bool need = (key_score(g2) - key_score(g1) < MARGIN);
            if (need) {
                float4 e0 = scr2[gr * 2 + 0], e1 = scr2[gr * 2 + 1];
                float ev1 = e0.x, ev2 = e0.z;
                int   ek1 = __float_as_int(e0.y), ek2 = __float_as_int(e0.w);
                merge_top2(ev1, ek1, ev2, ek2,
                           e1.x, __float_as_int(e1.y), e1.z, __float_as_int(e1.w));
                widx = ek1;
                if (ek2 != 0x7fffffff && ev2 - ev1 < 3e-4f && (L & 3) == 0) {
                    int ka = min(ek1, ek2), kb = max(ek1, ek2);
                    widx = vote_tie(x, m0 + gr, ka, kb);
                }
            }
            if ((L & 3) == 0) bidx[gr] = widx;
        }
    }
    __syncthreads();

    // epilogue: out = x + (q - x), loss  (512 threads: 2 rows per step)
    float lsum = 0.f;
    int d = tid & 255;
    for (int m = tid >> 8; m < H_MBLK; m += 2) {
        int idx = bidx[m];
        float q  = g_eT[(size_t)idx * DIMS + d];
        float xv = x[(size_t)(m0 + m) * DIMS + d];
        out[(size_t)(m0 + m) * DIMS + d] = __fadd_rn(xv, __fsub_rn(q, xv));
        float dq = __fsub_rn(q, xv);
        lsum = fmaf(dq, dq, lsum);
    }
#pragma unroll
    for (int off = 16; off; off >>= 1)
        lsum += __shfl_xor_sync(0xffffffffu, lsum, off);
    __shared__ float wsum[16];
    if (L == 0) wsum[w] = lsum;
    __syncthreads();
    if (tid == 0) {
        float t = 0.f;
#pragma unroll
        for (int q = 0; q < 16; q++) t += wsum[q];
        atomicAdd(&g_loss, (double)t);
    }
}

__global__ void finalize_kernel(float* __restrict__ out, long long loss_index) {
    if (threadIdx.x == 0) {
        float m = (float)(g_loss / (double)((long long)N_VEC * DIMS));
        out[loss_index] = __fadd_rn(__fmul_rn(0.25f, m), m);
    }
}

// ---------------------------------------------------------------------------
extern "C" void kernel_launch(void* const* d_in, const int* in_sizes, int n_in,
                              void* d_out, int out_size) {
    const float* x   = (const float*)d_in[0];
    const float* emb = (const float*)d_in[1];
    float* out = (float*)d_out;

    dim3 tb(32, 8);
    transpose_e_kernel<<<dim3(KCODES / 32, DIMS / 32), tb>>>(emb);
    enorm_kernel<<<KCODES / 8, 256>>>();
    convert_aug_kernel<<<(KCODES * 34 + 255) / 256, 256>>>();

    cudaFuncSetAttribute(vq_hmma_kernel,
                         cudaFuncAttributeMaxDynamicSharedMemorySize, SMH_TOTAL);
    vq_hmma_kernel<<<N_VEC / H_MBLK, HT, SMH_TOTAL>>>(x, out);

    finalize_kernel<<<1, 32>>>(out, (long long)out_size - 1);
}

// round 12
// speedup vs baseline: 1.5002x; 1.5002x over previous
#include <cuda_runtime.h>
#include <cuda_bf16.h>
#include <cstdint>
#include <float.h>

#define N_VEC    32768
#define DIMS     256
#define KCODES   1024
#define MARGIN   0.05f

// -------- device scratch ----------------------------------------------------
__device__ __align__(16) float          g_eT[KCODES * DIMS];    // fp32 codes [K][D]
__device__ __align__(16) __nv_bfloat16  g_etb[KCODES * DIMS];   // bf16 codes [K][D]
__device__ float  g_enorm2[KCODES];
__device__ double g_loss;

// -------- common helpers ------------------------------------------------------
__device__ __forceinline__ uint32_t smem_u32(const void* p) {
    uint32_t a;
    asm("{ .reg .u64 t; cvta.to.shared.u64 t, %1; cvt.u32.u64 %0, t; }"
        : "=r"(a) : "l"(p));
    return a;
}
__device__ __forceinline__ unsigned pack_bf2(float a, float b) {
    __nv_bfloat162 h = __floats2bfloat162_rn(a, b);
    return *reinterpret_cast<unsigned*>(&h);
}
__device__ __forceinline__ bool better(float v, int k, float v2, int k2) {
    return (v < v2) || (v == v2 && k < k2);
}
__device__ __forceinline__ void merge_top2(float& v1, int& k1, float& v2, int& k2,
                                           float ov1, int ok1, float ov2, int ok2) {
    float m1v, m2v; int m1k, m2k;
    if (better(v1, k1, ov1, ok1)) {
        m1v = v1; m1k = k1;
        if (better(v2, k2, ov1, ok1)) { m2v = v2; m2k = k2; }
        else                          { m2v = ov1; m2k = ok1; }
    } else {
        m1v = ov1; m1k = ok1;
        if (better(ov2, ok2, v1, k1)) { m2v = ov2; m2k = ok2; }
        else                          { m2v = v1;  m2k = k1;  }
    }
    v1 = m1v; k1 = m1k; v2 = m2v; k2 = m2k;
}

// reference-rounding-emulation tie vote (identical to the rel_err=0 round-2 code)
__device__ int vote_tie(const float* __restrict__ x, int v, int ka, int kb) {
    const float* xr = x + (size_t)v * DIMS;
    const float* ea = g_eT + (size_t)ka * DIMS;
    const float* eb = g_eT + (size_t)kb * DIMS;
    double sA = 0.0, sBa = 0.0, sBb = 0.0;
    for (int d = 0; d < DIMS; d++) {
        double xv = (double)xr[d];
        sA  += xv * xv;
        sBa += xv * (double)ea[d];
        sBb += xv * (double)eb[d];
    }
    float Ba = (float)sBa, Bb = (float)sBb;
    float Ca = g_enorm2[ka], Cb = g_enorm2[kb];
    int ab = __float_as_int((float)sA);
    int votes = 0;
#pragma unroll
    for (int jj = -2; jj <= 2; jj++) {
        int w = 3 - (jj < 0 ? -jj : jj);
        float Aj = __int_as_float(ab + jj);
        float da = __fadd_rn(__fsub_rn(Aj, __fmul_rn(2.f, Ba)), Ca);
        float db = __fadd_rn(__fsub_rn(Aj, __fmul_rn(2.f, Bb)), Cb);
        if (da <= db) votes += w;
    }
    return (votes >= 5) ? ka : kb;
}

__device__ __forceinline__ float exact_score(const float4* xr, int k, float enk) {
    const float4* er = (const float4*)(g_eT + (size_t)k * DIMS);
    float a0 = 0.f, a1 = 0.f, a2 = 0.f, a3 = 0.f;
#pragma unroll 8
    for (int d4 = 0; d4 < DIMS / 4; d4++) {
        float4 xv = __ldg(xr + d4), ev = __ldg(er + d4);
        a0 = fmaf(xv.x, ev.x, a0); a1 = fmaf(xv.y, ev.y, a1);
        a2 = fmaf(xv.z, ev.z, a2); a3 = fmaf(xv.w, ev.w, a3);
    }
    return fmaf(-2.f, (a0 + a1) + (a2 + a3), enk);
}

// -------- pre-kernels ---------------------------------------------------------
__global__ void transpose_e_kernel(const float* __restrict__ e) {
    __shared__ float tile[32][33];
    int k0 = blockIdx.x * 32, d0 = blockIdx.y * 32;
    int tx = threadIdx.x, ty = threadIdx.y;
#pragma unroll
    for (int i = ty; i < 32; i += 8)
        tile[i][tx] = e[(size_t)(d0 + i) * KCODES + k0 + tx];
    __syncthreads();
#pragma unroll
    for (int j = ty; j < 32; j += 8)
        g_eT[(size_t)(k0 + j) * DIMS + d0 + tx] = tile[tx][j];
}

__global__ void enorm_kernel() {
    int k = blockIdx.x * 8 + (threadIdx.x >> 5);
    int lane = threadIdx.x & 31;
    const float* row = g_eT + (size_t)k * DIMS;
    double s = 0.0;
#pragma unroll
    for (int j = 0; j < 8; j++) {
        double v = (double)row[lane + 32 * j];
        s += v * v;
    }
#pragma unroll
    for (int off = 16; off; off >>= 1)
        s += __shfl_xor_sync(0xffffffffu, s, off);
    if (lane == 0) g_enorm2[k] = (float)s;
    if (blockIdx.x == 0 && threadIdx.x == 0) g_loss = 0.0;
}

__global__ void convert_etb_kernel() {
    int i = blockIdx.x * 256 + threadIdx.x;
    const float4* s = (const float4*)g_eT;
    float4 f0 = s[i * 2], f1 = s[i * 2 + 1];
    uint4 d;
    d.x = pack_bf2(f0.x, f0.y); d.y = pack_bf2(f0.z, f0.w);
    d.z = pack_bf2(f1.x, f1.y); d.w = pack_bf2(f1.z, f1.w);
    ((uint4*)g_etb)[i] = d;
}

// ============================================================================
// HMMA main kernel — 2 CTAs/SM, single barrier per chunk, split-K acc chains
// ============================================================================
#define HT        512
#define H_MBLK    128
#define H_NCH     32
#define H_NCHUNKS 32
#define H_RSTRIDE 528                 // padded row stride (bytes) = 264 bf16
#define SMH_ENS   0                                // 4096 B
#define SMH_BIDX  4096                             // 512 B
#define SMH_SCR   4608                             // 4096 B (row x half x top2)
#define SMH_A     8704                             // 128*528 = 67584
#define SMH_B     (SMH_A + 128 * H_RSTRIDE)        // 76288
#define H_BUFSZ   (32 * H_RSTRIDE)                 // 16896
#define SMH_TOTAL (SMH_B + 2 * H_BUFSZ)            // 110080

__device__ __forceinline__ void cp16(uint32_t dst, const void* src) {
    asm volatile("cp.async.cg.shared.global [%0], [%1], 16;"
                 :: "r"(dst), "l"(src) : "memory");
}
#define CP_COMMIT() asm volatile("cp.async.commit_group;" ::: "memory")
#define CP_WAIT0()  asm volatile("cp.async.wait_group 0;" ::: "memory")

__device__ __forceinline__ void ldsm4(uint32_t* r, uint32_t addr) {
    asm volatile("ldmatrix.sync.aligned.m8n8.x4.shared.b16 {%0,%1,%2,%3}, [%4];"
                 : "=r"(r[0]), "=r"(r[1]), "=r"(r[2]), "=r"(r[3]) : "r"(addr));
}
__device__ __forceinline__ void mma16816(float* c, const uint32_t* a,
                                         uint32_t b0, uint32_t b1) {
    asm volatile("mma.sync.aligned.m16n8k16.row.col.f32.bf16.bf16.f32 "
                 "{%0,%1,%2,%3}, {%4,%5,%6,%7}, {%8,%9}, {%0,%1,%2,%3};"
                 : "+f"(c[0]), "+f"(c[1]), "+f"(c[2]), "+f"(c[3])
                 : "r"(a[0]), "r"(a[1]), "r"(a[2]), "r"(a[3]), "r"(b0), "r"(b1));
}

__global__ void __launch_bounds__(HT, 2)
vq_hmma_kernel(const float* __restrict__ x, float* __restrict__ out) {
    extern __shared__ char smem[];
    uint32_t sb = smem_u32(smem);
    float*  ens  = (float*)(smem + SMH_ENS);
    int*    bidx = (int*)(smem + SMH_BIDX);
    float4* scr  = (float4*)(smem + SMH_SCR);      // [128][2] warp-half top2
    float4* scr2 = (float4*)(smem + SMH_B);        // reused after mainloop
    int tid = threadIdx.x, w = tid >> 5, L = tid & 31;
    int wm = w >> 1, wn = w & 1;
    int m0 = blockIdx.x * H_MBLK;

    for (int i = tid; i < KCODES; i += HT) ens[i] = g_enorm2[i];

    // A tile: x fp32 -> bf16, padded-stride smem [128][264 bf16]
    const float4* xs = (const float4*)x;
    for (int u = tid; u < 4096; u += HT) {
        int row = u >> 5, c = u & 31;
        size_t s4 = ((size_t)(m0 + row)) * 64 + c * 2;
        float4 f0 = __ldg(xs + s4), f1 = __ldg(xs + s4 + 1);
        uint4 d;
        d.x = pack_bf2(f0.x, f0.y); d.y = pack_bf2(f0.z, f0.w);
        d.z = pack_bf2(f1.x, f1.y); d.w = pack_bf2(f1.z, f1.w);
        *(uint4*)(smem + SMH_A + row * H_RSTRIDE + c * 16) = d;
    }
    // preload B chunk 0
    {
        const char* ebase = (const char*)g_etb;
        for (int u = tid; u < 1024; u += HT)
            cp16(sb + SMH_B + (u >> 5) * H_RSTRIDE + (u & 31) * 16,
                 ebase + (size_t)(u >> 5) * 512 + (u & 31) * 16);
        CP_COMMIT();
    }

    // lane-dependent ldmatrix address parts
    uint32_t a_lane = sb + SMH_A + (uint32_t)(wm * 16 + (L & 15)) * H_RSTRIDE
                    + (uint32_t)(L >> 4) * 16;
    uint32_t b_lane = (uint32_t)(wn * 16 + (L & 7) + ((L >> 4) << 3)) * H_RSTRIDE
                    + (uint32_t)((L >> 3) & 1) * 16;

    // per-lane running top-3 for 2 rows: wm*16 + {0,8} + (L>>2)
    float hv1[2], hv2[2], hv3[2]; int hk1[2], hk2[2], hk3[2];
#pragma unroll
    for (int q = 0; q < 2; q++) {
        hv1[q] = FLT_MAX; hv2[q] = FLT_MAX; hv3[q] = FLT_MAX;
        hk1[q] = 0x7fffffff; hk2[q] = 0x7fffffff; hk3[q] = 0x7fffffff;
    }

#define UPD(ri, kk, vv) do {                                                    \
    float s_ = fmaf(-2.f, (vv), ens[(kk)]);                                     \
    if (s_ < hv3[ri]) {                                                         \
        if (s_ < hv1[ri]) {                                                     \
            hv3[ri] = hv2[ri]; hk3[ri] = hk2[ri];                               \
            hv2[ri] = hv1[ri]; hk2[ri] = hk1[ri];                               \
            hv1[ri] = s_; hk1[ri] = (kk);                                       \
        } else if (s_ < hv2[ri]) {                                              \
            hv3[ri] = hv2[ri]; hk3[ri] = hk2[ri];                               \
            hv2[ri] = s_; hk2[ri] = (kk);                                       \
        } else { hv3[ri] = s_; hk3[ri] = (kk); }                                \
    } } while (0)

    for (int i = 0; i < H_NCHUNKS; i++) {
        // single barrier per chunk: publishes chunk i AND frees buf (i+1)&1
        CP_WAIT0();
        __syncthreads();
        if (i + 1 < H_NCHUNKS) {
            const char* ebase = (const char*)g_etb + (size_t)(i + 1) * H_NCH * 512;
            uint32_t bdst = sb + SMH_B + ((i + 1) & 1) * H_BUFSZ;
            for (int u = tid; u < 1024; u += HT)
                cp16(bdst + (u >> 5) * H_RSTRIDE + (u & 31) * 16,
                     ebase + (size_t)(u >> 5) * 512 + (u & 31) * 16);
            CP_COMMIT();
        }

        uint32_t bbase = sb + SMH_B + (i & 1) * H_BUFSZ + b_lane;

        // split-K accumulators: [ni][ks&1][4] -> chain depth 8, 4 chains
        float acc[2][2][4];
#pragma unroll
        for (int ni = 0; ni < 2; ni++)
#pragma unroll
            for (int p = 0; p < 2; p++)
#pragma unroll
                for (int c = 0; c < 4; c++) acc[ni][p][c] = 0.f;

#pragma unroll 4
        for (int ks = 0; ks < 16; ks++) {
            uint32_t af[4], bf[4];
            ldsm4(af, a_lane + ks * 32);
            ldsm4(bf, bbase + ks * 32);
            mma16816(acc[0][ks & 1], af, bf[0], bf[1]);
            mma16816(acc[1][ks & 1], af, bf[2], bf[3]);
        }

        int kb = i * H_NCH + wn * 16 + (L & 3) * 2;
#pragma unroll
        for (int c = 0; c < 4; c++) {
            acc[0][0][c] += acc[0][1][c];
            acc[1][0][c] += acc[1][1][c];
        }
        UPD(0, kb,     acc[0][0][0]); UPD(0, kb + 1, acc[0][0][1]);
        UPD(1, kb,     acc[0][0][2]); UPD(1, kb + 1, acc[0][0][3]);
        UPD(0, kb + 8, acc[1][0][0]); UPD(0, kb + 9, acc[1][0][1]);
        UPD(1, kb + 8, acc[1][0][2]); UPD(1, kb + 9, acc[1][0][3]);
    }
#undef UPD
    __syncthreads();                               // mainloop done; reuse smem

    // ---- decision: quad merge -> smem cross-half merge -> rescue -> vote ----
#pragma unroll
    for (int ri = 0; ri < 2; ri++) {
        float v1 = hv1[ri], v2 = hv2[ri];
        int   k1 = hk1[ri], k2 = hk2[ri];
#pragma unroll
        for (int off = 1; off <= 2; off <<= 1) {
            float ov1 = __shfl_xor_sync(0xffffffffu, v1, off);
            int   ok1 = __shfl_xor_sync(0xffffffffu, k1, off);
            float ov2 = __shfl_xor_sync(0xffffffffu, v2, off);
            int   ok2 = __shfl_xor_sync(0xffffffffu, k2, off);
            merge_top2(v1, k1, v2, k2, ov1, ok1, ov2, ok2);
        }
        if ((L & 3) == 0) {
            int gr = wm * 16 + ri * 8 + (L >> 2);
            scr[gr * 2 + wn] = make_float4(v1, __int_as_float(k1),
                                           v2, __int_as_float(k2));
        }
    }
    __syncthreads();

#pragma unroll 1
    for (int ri = 0; ri < 2; ri++) {
        int gr = wm * 16 + ri * 8 + (L >> 2);
        float4 h0 = scr[gr * 2 + 0], h1 = scr[gr * 2 + 1];
        float gv1 = h0.x, gv2 = h0.z;
        int   gk1 = __float_as_int(h0.y), gk2 = __float_as_int(h0.w);
        merge_top2(gv1, gk1, gv2, gk2,
                   h1.x, __float_as_int(h1.y), h1.z, __float_as_int(h1.w));
        bool need = (gv2 - gv1 < MARGIN);
        float ev1 = FLT_MAX, ev2 = FLT_MAX;
        int   ek1 = 0x7fffffff, ek2 = 0x7fffffff;
        if (__any_sync(0xffffffffu, need)) {
            if (need) {
                float lim = gv1 + MARGIN;
                const float4* xr = (const float4*)(x + (size_t)(m0 + gr) * DIMS);
                float cv[3] = { hv1[ri], hv2[ri], hv3[ri] };
                int   ck[3] = { hk1[ri], hk2[ri], hk3[ri] };
#pragma unroll
                for (int c = 0; c < 3; c++) {
                    if (cv[c] <= lim && ck[c] != 0x7fffffff) {
                        int kc = ck[c];
                        float s = exact_score(xr, kc, ens[kc]);
                        if (s < ev1 || (s == ev1 && kc < ek1)) {
                            ev2 = ev1; ek2 = ek1; ev1 = s; ek1 = kc;
                        } else if (s < ev2 || (s == ev2 && kc < ek2)) {
                            ev2 = s; ek2 = kc;
                        }
                    }
                }
            }
#pragma unroll
            for (int off = 1; off <= 2; off <<= 1) {
                float ov1 = __shfl_xor_sync(0xffffffffu, ev1, off);
                int   ok1 = __shfl_xor_sync(0xffffffffu, ek1, off);
                float ov2 = __shfl_xor_sync(0xffffffffu, ev2, off);
                int   ok2 = __shfl_xor_sync(0xffffffffu, ek2, off);
                merge_top2(ev1, ek1, ev2, ek2, ov1, ok1, ov2, ok2);
            }
        }
        if ((L & 3) == 0)
            scr2[gr * 2 + wn] = make_float4(ev1, __int_as_float(ek1),
                                            ev2, __int_as_float(ek2));
    }
    __syncthreads();

    if (wn == 0) {
#pragma unroll 1
        for (int ri = 0; ri < 2; ri++) {
            int gr = wm * 16 + ri * 8 + (L >> 2);
            float4 h0 = scr[gr * 2 + 0], h1 = scr[gr * 2 + 1];
            float gv1 = h0.x, gv2 = h0.z;
            int   gk1 = __float_as_int(h0.y), gk2 = __float_as_int(h0.w);
            merge_top2(gv1, gk1, gv2, gk2,
                       h1.x, __float_as_int(h1.y), h1.z, __float_as_int(h1.w));
            int widx = gk1;
            bool need = (gv2 - gv1 < MARGIN);
            if (need) {
                float4 e0 = scr2[gr * 2 + 0], e1 = scr2[gr * 2 + 1];
                float ev1 = e0.x, ev2 = e0.z;
                int   ek1 = __float_as_int(e0.y), ek2 = __float_as_int(e0.w);
                merge_top2(ev1, ek1, ev2, ek2,
                           e1.x, __float_as_int(e1.y), e1.z, __float_as_int(e1.w));
                widx = ek1;
                if (ek2 != 0x7fffffff && ev2 - ev1 < 3e-4f && (L & 3) == 0) {
                    int ka = min(ek1, ek2), kb = max(ek1, ek2);
                    widx = vote_tie(x, m0 + gr, ka, kb);
                }
            }
            if ((L & 3) == 0) bidx[gr] = widx;
        }
    }
    __syncthreads();

    // epilogue: out = x + (q - x), loss  (512 threads: 2 rows per step)
    float lsum = 0.f;
    int d = tid & 255;
    for (int m = tid >> 8; m < H_MBLK; m += 2) {
        int idx = bidx[m];
        float q  = g_eT[(size_t)idx * DIMS + d];
        float xv = x[(size_t)(m0 + m) * DIMS + d];
        out[(size_t)(m0 + m) * DIMS + d] = __fadd_rn(xv, __fsub_rn(q, xv));
        float dq = __fsub_rn(q, xv);
        lsum = fmaf(dq, dq, lsum);
    }
#pragma unroll
    for (int off = 16; off; off >>= 1)
        lsum += __shfl_xor_sync(0xffffffffu, lsum, off);
    __shared__ float wsum[16];
    if (L == 0) wsum[w] = lsum;
    __syncthreads();
    if (tid == 0) {
        float t = 0.f;
#pragma unroll
        for (int q = 0; q < 16; q++) t += wsum[q];
        atomicAdd(&g_loss, (double)t);
    }
}

__global__ void finalize_kernel(float* __restrict__ out, long long loss_index) {
    if (threadIdx.x == 0) {
        float m = (float)(g_loss / (double)((long long)N_VEC * DIMS));
        out[loss_index] = __fadd_rn(__fmul_rn(0.25f, m), m);
    }
}

// ---------------------------------------------------------------------------
extern "C" void kernel_launch(void* const* d_in, const int* in_sizes, int n_in,
                              void* d_out, int out_size) {
    const float* x   = (const float*)d_in[0];
    const float* emb = (const float*)d_in[1];
    float* out = (float*)d_out;

    dim3 tb(32, 8);
    transpose_e_kernel<<<dim3(KCODES / 32, DIMS / 32), tb>>>(emb);
    enorm_kernel<<<KCODES / 8, 256>>>();
    convert_etb_kernel<<<128, 256>>>();

    cudaFuncSetAttribute(vq_hmma_kernel,
                         cudaFuncAttributeMaxDynamicSharedMemorySize, SMH_TOTAL);
    vq_hmma_kernel<<<N_VEC / H_MBLK, HT, SMH_TOTAL>>>(x, out);

    finalize_kernel<<<1, 32>>>(out, (long long)out_size - 1);
}

// round 13
// speedup vs baseline: 1.5407x; 1.0270x over previous
#include <cuda_runtime.h>
#include <cuda_bf16.h>
#include <cstdint>
#include <float.h>

#define N_VEC    32768
#define DIMS     256
#define KCODES   1024
#define MARGIN   0.06f

// -------- device scratch ----------------------------------------------------
__device__ __align__(16) float          g_eT[KCODES * DIMS];    // fp32 codes [K][D]
__device__ __align__(16) __nv_bfloat16  g_etb[KCODES * DIMS];   // bf16 codes [K][D]
__device__ float  g_enorm2[KCODES];
__device__ double g_loss;

// -------- common helpers ------------------------------------------------------
__device__ __forceinline__ uint32_t smem_u32(const void* p) {
    uint32_t a;
    asm("{ .reg .u64 t; cvta.to.shared.u64 t, %1; cvt.u32.u64 %0, t; }"
        : "=r"(a) : "l"(p));
    return a;
}
__device__ __forceinline__ unsigned pack_bf2(float a, float b) {
    __nv_bfloat162 h = __floats2bfloat162_rn(a, b);
    return *reinterpret_cast<unsigned*>(&h);
}
__device__ __forceinline__ bool better(float v, int k, float v2, int k2) {
    return (v < v2) || (v == v2 && k < k2);
}
__device__ __forceinline__ void merge_top2(float& v1, int& k1, float& v2, int& k2,
                                           float ov1, int ok1, float ov2, int ok2) {
    float m1v, m2v; int m1k, m2k;
    if (better(v1, k1, ov1, ok1)) {
        m1v = v1; m1k = k1;
        if (better(v2, k2, ov1, ok1)) { m2v = v2; m2k = k2; }
        else                          { m2v = ov1; m2k = ok1; }
    } else {
        m1v = ov1; m1k = ok1;
        if (better(ov2, ok2, v1, k1)) { m2v = ov2; m2k = ok2; }
        else                          { m2v = v1;  m2k = k1;  }
    }
    v1 = m1v; k1 = m1k; v2 = m2v; k2 = m2k;
}

// reference-rounding-emulation tie vote (identical to the rel_err=0 round-2 code)
__device__ int vote_tie(const float* __restrict__ x, int v, int ka, int kb) {
    const float* xr = x + (size_t)v * DIMS;
    const float* ea = g_eT + (size_t)ka * DIMS;
    const float* eb = g_eT + (size_t)kb * DIMS;
    double sA = 0.0, sBa = 0.0, sBb = 0.0;
    for (int d = 0; d < DIMS; d++) {
        double xv = (double)xr[d];
        sA  += xv * xv;
        sBa += xv * (double)ea[d];
        sBb += xv * (double)eb[d];
    }
    float Ba = (float)sBa, Bb = (float)sBb;
    float Ca = g_enorm2[ka], Cb = g_enorm2[kb];
    int ab = __float_as_int((float)sA);
    int votes = 0;
#pragma unroll
    for (int jj = -2; jj <= 2; jj++) {
        int w = 3 - (jj < 0 ? -jj : jj);
        float Aj = __int_as_float(ab + jj);
        float da = __fadd_rn(__fsub_rn(Aj, __fmul_rn(2.f, Ba)), Ca);
        float db = __fadd_rn(__fsub_rn(Aj, __fmul_rn(2.f, Bb)), Cb);
        if (da <= db) votes += w;
    }
    return (votes >= 5) ? ka : kb;
}

__device__ __forceinline__ float exact_score(const float4* xr, int k, float enk) {
    const float4* er = (const float4*)(g_eT + (size_t)k * DIMS);
    float a0 = 0.f, a1 = 0.f, a2 = 0.f, a3 = 0.f;
#pragma unroll 8
    for (int d4 = 0; d4 < DIMS / 4; d4++) {
        float4 xv = __ldg(xr + d4), ev = __ldg(er + d4);
        a0 = fmaf(xv.x, ev.x, a0); a1 = fmaf(xv.y, ev.y, a1);
        a2 = fmaf(xv.z, ev.z, a2); a3 = fmaf(xv.w, ev.w, a3);
    }
    return fmaf(-2.f, (a0 + a1) + (a2 + a3), enk);
}

// -------- pre-kernels ---------------------------------------------------------
__global__ void transpose_e_kernel(const float* __restrict__ e) {
    __shared__ float tile[32][33];
    int k0 = blockIdx.x * 32, d0 = blockIdx.y * 32;
    int tx = threadIdx.x, ty = threadIdx.y;
#pragma unroll
    for (int i = ty; i < 32; i += 8)
        tile[i][tx] = e[(size_t)(d0 + i) * KCODES + k0 + tx];
    __syncthreads();
#pragma unroll
    for (int j = ty; j < 32; j += 8)
        g_eT[(size_t)(k0 + j) * DIMS + d0 + tx] = tile[tx][j];
}

__global__ void enorm_kernel() {
    int k = blockIdx.x * 8 + (threadIdx.x >> 5);
    int lane = threadIdx.x & 31;
    const float* row = g_eT + (size_t)k * DIMS;
    double s = 0.0;
#pragma unroll
    for (int j = 0; j < 8; j++) {
        double v = (double)row[lane + 32 * j];
        s += v * v;
    }
#pragma unroll
    for (int off = 16; off; off >>= 1)
        s += __shfl_xor_sync(0xffffffffu, s, off);
    if (lane == 0) g_enorm2[k] = (float)s;
    if (blockIdx.x == 0 && threadIdx.x == 0) g_loss = 0.0;
}

__global__ void convert_etb_kernel() {
    int i = blockIdx.x * 256 + threadIdx.x;
    const float4* s = (const float4*)g_eT;
    float4 f0 = s[i * 2], f1 = s[i * 2 + 1];
    uint4 d;
    d.x = pack_bf2(f0.x, f0.y); d.y = pack_bf2(f0.z, f0.w);
    d.z = pack_bf2(f1.x, f1.y); d.w = pack_bf2(f1.z, f1.w);
    ((uint4*)g_etb)[i] = d;
}

// ============================================================================
// HMMA main kernel — R12 base + branchless packed-key top-3 in hot loop
// ============================================================================
#define HT        512
#define H_MBLK    128
#define H_NCH     32
#define H_NCHUNKS 32
#define H_RSTRIDE 528                 // padded row stride (bytes) = 264 bf16
#define SMH_ENS    0                               // 4096 B (exact ||e||^2)
#define SMH_ENS512 4096                            // 4096 B (||e||^2 + 512)
#define SMH_BIDX   8192                            // 512 B
#define SMH_SCR    8704                            // 4096 B (row x half x top2)
#define SMH_A      12800                           // 128*528 = 67584
#define SMH_B      (SMH_A + 128 * H_RSTRIDE)       // 80384
#define H_BUFSZ    (32 * H_RSTRIDE)                // 16896
#define SMH_TOTAL  (SMH_B + 2 * H_BUFSZ)           // 114176

__device__ __forceinline__ void cp16(uint32_t dst, const void* src) {
    asm volatile("cp.async.cg.shared.global [%0], [%1], 16;"
                 :: "r"(dst), "l"(src) : "memory");
}
#define CP_COMMIT() asm volatile("cp.async.commit_group;" ::: "memory")
#define CP_WAIT0()  asm volatile("cp.async.wait_group 0;" ::: "memory")

__device__ __forceinline__ void ldsm4(uint32_t* r, uint32_t addr) {
    asm volatile("ldmatrix.sync.aligned.m8n8.x4.shared.b16 {%0,%1,%2,%3}, [%4];"
                 : "=r"(r[0]), "=r"(r[1]), "=r"(r[2]), "=r"(r[3]) : "r"(addr));
}
__device__ __forceinline__ void mma16816(float* c, const uint32_t* a,
                                         uint32_t b0, uint32_t b1) {
    asm volatile("mma.sync.aligned.m16n8k16.row.col.f32.bf16.bf16.f32 "
                 "{%0,%1,%2,%3}, {%4,%5,%6,%7}, {%8,%9}, {%0,%1,%2,%3};"
                 : "+f"(c[0]), "+f"(c[1]), "+f"(c[2]), "+f"(c[3])
                 : "r"(a[0]), "r"(a[1]), "r"(a[2]), "r"(a[3]), "r"(b0), "r"(b1));
}

// decode lane-local packed key (quantized score, global code index)
__device__ __forceinline__ float key_s(uint32_t key) {
    return __uint_as_float(key & 0xFFFFFF80u) - 512.f;
}
__device__ __forceinline__ int key_kk(uint32_t key, int wn, int L) {
    int li = (int)(key & 0x7Fu);
    int c  = li & 3;
    return ((li >> 2) << 5) + wn * 16 + (L & 3) * 2 + ((c & 2) << 2) + (c & 1);
}

__global__ void __launch_bounds__(HT, 2)
vq_hmma_kernel(const float* __restrict__ x, float* __restrict__ out) {
    extern __shared__ char smem[];
    uint32_t sb = smem_u32(smem);
    float*  ens  = (float*)(smem + SMH_ENS);
    float*  e512 = (float*)(smem + SMH_ENS512);
    int*    bidx = (int*)(smem + SMH_BIDX);
    float4* scr  = (float4*)(smem + SMH_SCR);      // [128][2] warp-half top2
    float4* scr2 = (float4*)(smem + SMH_B);        // reused after mainloop
    int tid = threadIdx.x, w = tid >> 5, L = tid & 31;
    int wm = w >> 1, wn = w & 1;
    int m0 = blockIdx.x * H_MBLK;

    for (int i = tid; i < KCODES; i += HT) {
        float e = g_enorm2[i];
        ens[i]  = e;
        e512[i] = e + 512.f;
    }

    // A tile: x fp32 -> bf16, padded-stride smem [128][264 bf16]
    const float4* xs = (const float4*)x;
    for (int u = tid; u < 4096; u += HT) {
        int row = u >> 5, c = u & 31;
        size_t s4 = ((size_t)(m0 + row)) * 64 + c * 2;
        float4 f0 = __ldg(xs + s4), f1 = __ldg(xs + s4 + 1);
        uint4 d;
        d.x = pack_bf2(f0.x, f0.y); d.y = pack_bf2(f0.z, f0.w);
        d.z = pack_bf2(f1.x, f1.y); d.w = pack_bf2(f1.z, f1.w);
        *(uint4*)(smem + SMH_A + row * H_RSTRIDE + c * 16) = d;
    }
    // preload B chunk 0
    {
        const char* ebase = (const char*)g_etb;
        for (int u = tid; u < 1024; u += HT)
            cp16(sb + SMH_B + (u >> 5) * H_RSTRIDE + (u & 31) * 16,
                 ebase + (size_t)(u >> 5) * 512 + (u & 31) * 16);
        CP_COMMIT();
    }

    // lane-dependent ldmatrix address parts
    uint32_t a_lane = sb + SMH_A + (uint32_t)(wm * 16 + (L & 15)) * H_RSTRIDE
                    + (uint32_t)(L >> 4) * 16;
    uint32_t b_lane = (uint32_t)(wn * 16 + (L & 7) + ((L >> 4) << 3)) * H_RSTRIDE
                    + (uint32_t)((L >> 3) & 1) * 16;

    // branchless packed-key top-3 (ascending) for 2 rows; key = sbits|li
    uint32_t m1[2], m2[2], m3[2];
#pragma unroll
    for (int q = 0; q < 2; q++) { m1[q] = ~0u; m2[q] = ~0u; m3[q] = ~0u; }

#define UPDP(ri, e_, li_, vv) do {                                              \
    float s_ = fmaf(-2.f, (vv), (e_));                                          \
    uint32_t key_ = (__float_as_uint(s_) & 0xFFFFFF80u) | (uint32_t)(li_);      \
    uint32_t lo1_ = umin(m1[ri], key_);                                         \
    uint32_t hi1_ = umax(m1[ri], key_); m1[ri] = lo1_;                          \
    uint32_t lo2_ = umin(m2[ri], hi1_);                                         \
    uint32_t hi2_ = umax(m2[ri], hi1_); m2[ri] = lo2_;                          \
    m3[ri] = umin(m3[ri], hi2_);                                                \
} while (0)

    for (int i = 0; i < H_NCHUNKS; i++) {
        // single barrier per chunk: publishes chunk i AND frees buf (i+1)&1
        CP_WAIT0();
        __syncthreads();
        if (i + 1 < H_NCHUNKS) {
            const char* ebase = (const char*)g_etb + (size_t)(i + 1) * H_NCH * 512;
            uint32_t bdst = sb + SMH_B + ((i + 1) & 1) * H_BUFSZ;
            for (int u = tid; u < 1024; u += HT)
                cp16(bdst + (u >> 5) * H_RSTRIDE + (u & 31) * 16,
                     ebase + (size_t)(u >> 5) * 512 + (u & 31) * 16);
            CP_COMMIT();
        }

        uint32_t bbase = sb + SMH_B + (i & 1) * H_BUFSZ + b_lane;

        // split-K accumulators: [ni][ks&1][4] -> chain depth 8, 4 chains
        float acc[2][2][4];
#pragma unroll
        for (int ni = 0; ni < 2; ni++)
#pragma unroll
            for (int p = 0; p < 2; p++)
#pragma unroll
                for (int c = 0; c < 4; c++) acc[ni][p][c] = 0.f;

#pragma unroll 4
        for (int ks = 0; ks < 16; ks++) {
            uint32_t af[4], bf[4];
            ldsm4(af, a_lane + ks * 32);
            ldsm4(bf, bbase + ks * 32);
            mma16816(acc[0][ks & 1], af, bf[0], bf[1]);
            mma16816(acc[1][ks & 1], af, bf[2], bf[3]);
        }

        int kb = i * H_NCH + wn * 16 + (L & 3) * 2;
        int li = i * 4;
#pragma unroll
        for (int c = 0; c < 4; c++) {
            acc[0][0][c] += acc[0][1][c];
            acc[1][0][c] += acc[1][1][c];
        }
        float2 e01 = *(const float2*)(e512 + kb);
        float2 e89 = *(const float2*)(e512 + kb + 8);
        UPDP(0, e01.x, li,     acc[0][0][0]); UPDP(0, e01.y, li + 1, acc[0][0][1]);
        UPDP(1, e01.x, li,     acc[0][0][2]); UPDP(1, e01.y, li + 1, acc[0][0][3]);
        UPDP(0, e89.x, li + 2, acc[1][0][0]); UPDP(0, e89.y, li + 3, acc[1][0][1]);
        UPDP(1, e89.x, li + 2, acc[1][0][2]); UPDP(1, e89.y, li + 3, acc[1][0][3]);
    }
#undef UPDP
    __syncthreads();                               // mainloop done; reuse smem

    // decode packed keys -> (quantized score, global k); then R12 decision path
    float hv1[2], hv2[2], hv3[2]; int hk1[2], hk2[2], hk3[2];
#pragma unroll
    for (int q = 0; q < 2; q++) {
        hv1[q] = key_s(m1[q]); hk1[q] = key_kk(m1[q], wn, L);
        hv2[q] = key_s(m2[q]); hk2[q] = key_kk(m2[q], wn, L);
        hv3[q] = key_s(m3[q]); hk3[q] = key_kk(m3[q], wn, L);
    }

    // ---- decision: quad merge -> smem cross-half merge -> rescue -> vote ----
#pragma unroll
    for (int ri = 0; ri < 2; ri++) {
        float v1 = hv1[ri], v2 = hv2[ri];
        int   k1 = hk1[ri], k2 = hk2[ri];
#pragma unroll
        for (int off = 1; off <= 2; off <<= 1) {
            float ov1 = __shfl_xor_sync(0xffffffffu, v1, off);
            int   ok1 = __shfl_xor_sync(0xffffffffu, k1, off);
            float ov2 = __shfl_xor_sync(0xffffffffu, v2, off);
            int   ok2 = __shfl_xor_sync(0xffffffffu, k2, off);
            merge_top2(v1, k1, v2, k2, ov1, ok1, ov2, ok2);
        }
        if ((L & 3) == 0) {
            int gr = wm * 16 + ri * 8 + (L >> 2);
            scr[gr * 2 + wn] = make_float4(v1, __int_as_float(k1),
                                           v2, __int_as_float(k2));
        }
    }
    __syncthreads();

#pragma unroll 1
    for (int ri = 0; ri < 2; ri++) {
        int gr = wm * 16 + ri * 8 + (L >> 2);
        float4 h0 = scr[gr * 2 + 0], h1 = scr[gr * 2 + 1];
        float gv1 = h0.x, gv2 = h0.z;
        int   gk1 = __float_as_int(h0.y), gk2 = __float_as_int(h0.w);
        merge_top2(gv1, gk1, gv2, gk2,
                   h1.x, __float_as_int(h1.y), h1.z, __float_as_int(h1.w));
        bool need = (gv2 - gv1 < MARGIN);
        float ev1 = FLT_MAX, ev2 = FLT_MAX;
        int   ek1 = 0x7fffffff, ek2 = 0x7fffffff;
        if (__any_sync(0xffffffffu, need)) {
            if (need) {
                float lim = gv1 + MARGIN;
                const float4* xr = (const float4*)(x + (size_t)(m0 + gr) * DIMS);
                float cv[3] = { hv1[ri], hv2[ri], hv3[ri] };
                int   ck[3] = { hk1[ri], hk2[ri], hk3[ri] };
#pragma unroll
                for (int c = 0; c < 3; c++) {
                    if (cv[c] <= lim) {
                        int kc = ck[c];
                        float s = exact_score(xr, kc, ens[kc]);
                        if (s < ev1 || (s == ev1 && kc < ek1)) {
                            ev2 = ev1; ek2 = ek1; ev1 = s; ek1 = kc;
                        } else if (s < ev2 || (s == ev2 && kc < ek2)) {
                            ev2 = s; ek2 = kc;
                        }
                    }
                }
            }
#pragma unroll
            for (int off = 1; off <= 2; off <<= 1) {
                float ov1 = __shfl_xor_sync(0xffffffffu, ev1, off);
                int   ok1 = __shfl_xor_sync(0xffffffffu, ek1, off);
                float ov2 = __shfl_xor_sync(0xffffffffu, ev2, off);
                int   ok2 = __shfl_xor_sync(0xffffffffu, ek2, off);
                merge_top2(ev1, ek1, ev2, ek2, ov1, ok1, ov2, ok2);
            }
        }
        if ((L & 3) == 0)
            scr2[gr * 2 + wn] = make_float4(ev1, __int_as_float(ek1),
                                            ev2, __int_as_float(ek2));
    }
    __syncthreads();

    if (wn == 0) {
#pragma unroll 1
        for (int ri = 0; ri < 2; ri++) {
            int gr = wm * 16 + ri * 8 + (L >> 2);
            float4 h0 = scr[gr * 2 + 0], h1 = scr[gr * 2 + 1];
            float gv1 = h0.x, gv2 = h0.z;
            int   gk1 = __float_as_int(h0.y), gk2 = __float_as_int(h0.w);
            merge_top2(gv1, gk1, gv2, gk2,
                       h1.x, __float_as_int(h1.y), h1.z, __float_as_int(h1.w));
            int widx = gk1;
            bool need = (gv2 - gv1 < MARGIN);
            if (need) {
                float4 e0 = scr2[gr * 2 + 0], e1 = scr2[gr * 2 + 1];
                float ev1 = e0.x, ev2 = e0.z;
                int   ek1 = __float_as_int(e0.y), ek2 = __float_as_int(e0.w);
                merge_top2(ev1, ek1, ev2, ek2,
                           e1.x, __float_as_int(e1.y), e1.z, __float_as_int(e1.w));
                widx = ek1;
                if (ek2 != 0x7fffffff && ev2 - ev1 < 3e-4f && (L & 3) == 0) {
                    int ka = min(ek1, ek2), kb = max(ek1, ek2);
                    widx = vote_tie(x, m0 + gr, ka, kb);
                }
            }
            if ((L & 3) == 0) bidx[gr] = widx;
        }
    }
    __syncthreads();

    // epilogue: out = x + (q - x), loss  (512 threads: 2 rows per step)
    float lsum = 0.f;
    int d = tid & 255;
    for (int m = tid >> 8; m < H_MBLK; m += 2) {
        int idx = bidx[m];
        float q  = g_eT[(size_t)idx * DIMS + d];
        float xv = x[(size_t)(m0 + m) * DIMS + d];
        out[(size_t)(m0 + m) * DIMS + d] = __fadd_rn(xv, __fsub_rn(q, xv));
        float dq = __fsub_rn(q, xv);
        lsum = fmaf(dq, dq, lsum);
    }
#pragma unroll
    for (int off = 16; off; off >>= 1)
        lsum += __shfl_xor_sync(0xffffffffu, lsum, off);
    __shared__ float wsum[16];
    if (L == 0) wsum[w] = lsum;
    __syncthreads();
    if (tid == 0) {
        float t = 0.f;
#pragma unroll
        for (int q = 0; q < 16; q++) t += wsum[q];
        atomicAdd(&g_loss, (double)t);
    }
}

__global__ void finalize_kernel(float* __restrict__ out, long long loss_index) {
    if (threadIdx.x == 0) {
        float m = (float)(g_loss / (double)((long long)N_VEC * DIMS));
        out[loss_index] = __fadd_rn(__fmul_rn(0.25f, m), m);
    }
}

// ---------------------------------------------------------------------------
extern "C" void kernel_launch(void* const* d_in, const int* in_sizes, int n_in,
                              void* d_out, int out_size) {
    const float* x   = (const float*)d_in[0];
    const float* emb = (const float*)d_in[1];
    float* out = (float*)d_out;

    dim3 tb(32, 8);
    transpose_e_kernel<<<dim3(KCODES / 32, DIMS / 32), tb>>>(emb);
    enorm_kernel<<<KCODES / 8, 256>>>();
    convert_etb_kernel<<<128, 256>>>();

    cudaFuncSetAttribute(vq_hmma_kernel,
                         cudaFuncAttributeMaxDynamicSharedMemorySize, SMH_TOTAL);
    vq_hmma_kernel<<<N_VEC / H_MBLK, HT, SMH_TOTAL>>>(x, out);

    finalize_kernel<<<1, 32>>>(out, (long long)out_size - 1);
}

// round 14
// speedup vs baseline: 1.8061x; 1.1722x over previous
#include <cuda_runtime.h>
#include <cuda_bf16.h>
#include <cstdint>
#include <float.h>

#define N_VEC    32768
#define DIMS     256
#define KCODES   1024
#define MARGIN   0.09f

// -------- device scratch ----------------------------------------------------
__device__ __align__(16) float          g_eT[KCODES * DIMS];    // fp32 codes [K][D]
__device__ __align__(16) __nv_bfloat16  g_etb[KCODES * DIMS];   // bf16 codes [K][D]
__device__ float  g_enorm2[KCODES];
__device__ double g_loss;

// -------- common helpers ------------------------------------------------------
__device__ __forceinline__ uint32_t smem_u32(const void* p) {
    uint32_t a;
    asm("{ .reg .u64 t; cvta.to.shared.u64 t, %1; cvt.u32.u64 %0, t; }"
        : "=r"(a) : "l"(p));
    return a;
}
__device__ __forceinline__ unsigned pack_bf2(float a, float b) {
    __nv_bfloat162 h = __floats2bfloat162_rn(a, b);
    return *reinterpret_cast<unsigned*>(&h);
}
__device__ __forceinline__ bool better(float v, int k, float v2, int k2) {
    return (v < v2) || (v == v2 && k < k2);
}
__device__ __forceinline__ void merge_top2(float& v1, int& k1, float& v2, int& k2,
                                           float ov1, int ok1, float ov2, int ok2) {
    float m1v, m2v; int m1k, m2k;
    if (better(v1, k1, ov1, ok1)) {
        m1v = v1; m1k = k1;
        if (better(v2, k2, ov1, ok1)) { m2v = v2; m2k = k2; }
        else                          { m2v = ov1; m2k = ok1; }
    } else {
        m1v = ov1; m1k = ok1;
        if (better(ov2, ok2, v1, k1)) { m2v = ov2; m2k = ok2; }
        else                          { m2v = v1;  m2k = k1;  }
    }
    v1 = m1v; k1 = m1k; v2 = m2v; k2 = m2k;
}

// reference-rounding-emulation tie vote (identical to the rel_err=0 round-2 code)
__device__ int vote_tie(const float* __restrict__ x, int v, int ka, int kb) {
    const float* xr = x + (size_t)v * DIMS;
    const float* ea = g_eT + (size_t)ka * DIMS;
    const float* eb = g_eT + (size_t)kb * DIMS;
    double sA = 0.0, sBa = 0.0, sBb = 0.0;
    for (int d = 0; d < DIMS; d++) {
        double xv = (double)xr[d];
        sA  += xv * xv;
        sBa += xv * (double)ea[d];
        sBb += xv * (double)eb[d];
    }
    float Ba = (float)sBa, Bb = (float)sBb;
    float Ca = g_enorm2[ka], Cb = g_enorm2[kb];
    int ab = __float_as_int((float)sA);
    int votes = 0;
#pragma unroll
    for (int jj = -2; jj <= 2; jj++) {
        int w = 3 - (jj < 0 ? -jj : jj);
        float Aj = __int_as_float(ab + jj);
        float da = __fadd_rn(__fsub_rn(Aj, __fmul_rn(2.f, Ba)), Ca);
        float db = __fadd_rn(__fsub_rn(Aj, __fmul_rn(2.f, Bb)), Cb);
        if (da <= db) votes += w;
    }
    return (votes >= 5) ? ka : kb;
}

__device__ __forceinline__ float exact_score(const float4* xr, int k, float enk) {
    const float4* er = (const float4*)(g_eT + (size_t)k * DIMS);
    float a0 = 0.f, a1 = 0.f, a2 = 0.f, a3 = 0.f;
#pragma unroll 8
    for (int d4 = 0; d4 < DIMS / 4; d4++) {
        float4 xv = __ldg(xr + d4), ev = __ldg(er + d4);
        a0 = fmaf(xv.x, ev.x, a0); a1 = fmaf(xv.y, ev.y, a1);
        a2 = fmaf(xv.z, ev.z, a2); a3 = fmaf(xv.w, ev.w, a3);
    }
    return fmaf(-2.f, (a0 + a1) + (a2 + a3), enk);
}

// -------- pre-kernels ---------------------------------------------------------
__global__ void transpose_e_kernel(const float* __restrict__ e) {
    __shared__ float tile[32][33];
    int k0 = blockIdx.x * 32, d0 = blockIdx.y * 32;
    int tx = threadIdx.x, ty = threadIdx.y;
#pragma unroll
    for (int i = ty; i < 32; i += 8)
        tile[i][tx] = e[(size_t)(d0 + i) * KCODES + k0 + tx];
    __syncthreads();
#pragma unroll
    for (int j = ty; j < 32; j += 8)
        g_eT[(size_t)(k0 + j) * DIMS + d0 + tx] = tile[tx][j];
}

__global__ void enorm_kernel() {
    int k = blockIdx.x * 8 + (threadIdx.x >> 5);
    int lane = threadIdx.x & 31;
    const float* row = g_eT + (size_t)k * DIMS;
    double s = 0.0;
#pragma unroll
    for (int j = 0; j < 8; j++) {
        double v = (double)row[lane + 32 * j];
        s += v * v;
    }
#pragma unroll
    for (int off = 16; off; off >>= 1)
        s += __shfl_xor_sync(0xffffffffu, s, off);
    if (lane == 0) g_enorm2[k] = (float)s;
    if (blockIdx.x == 0 && threadIdx.x == 0) g_loss = 0.0;
}

__global__ void convert_etb_kernel() {
    int i = blockIdx.x * 256 + threadIdx.x;
    const float4* s = (const float4*)g_eT;
    float4 f0 = s[i * 2], f1 = s[i * 2 + 1];
    uint4 d;
    d.x = pack_bf2(f0.x, f0.y); d.y = pack_bf2(f0.z, f0.w);
    d.z = pack_bf2(f1.x, f1.y); d.w = pack_bf2(f1.z, f1.w);
    ((uint4*)g_etb)[i] = d;
}

// ============================================================================
// HMMA main kernel — A resident in registers, warp = m16 x n32, grid 128
// ============================================================================
#define HT        512
#define H_MBLK    256
#define H_NCH     32
#define H_NCHUNKS 32
#define H_RSTRIDE 528                 // padded row stride (bytes) = 264 bf16
#define SMH_ENS    0                               // 4096 B (exact ||e||^2)
#define SMH_ENS512 4096                            // 4096 B (||e||^2 + 512)
#define SMH_BIDX   8192                            // 1024 B (256 ints)
#define SMH_B      9216
#define H_BUFSZ    (32 * H_RSTRIDE)                // 16896
#define SMH_TOTAL  (SMH_B + 2 * H_BUFSZ)           // 43008

__device__ __forceinline__ void cp16(uint32_t dst, const void* src) {
    asm volatile("cp.async.cg.shared.global [%0], [%1], 16;"
                 :: "r"(dst), "l"(src) : "memory");
}
#define CP_COMMIT() asm volatile("cp.async.commit_group;" ::: "memory")
#define CP_WAIT0()  asm volatile("cp.async.wait_group 0;" ::: "memory")

__device__ __forceinline__ void ldsm4(uint32_t* r, uint32_t addr) {
    asm volatile("ldmatrix.sync.aligned.m8n8.x4.shared.b16 {%0,%1,%2,%3}, [%4];"
                 : "=r"(r[0]), "=r"(r[1]), "=r"(r[2]), "=r"(r[3]) : "r"(addr));
}
__device__ __forceinline__ void mma16816(float* c, const uint32_t* a,
                                         uint32_t b0, uint32_t b1) {
    asm volatile("mma.sync.aligned.m16n8k16.row.col.f32.bf16.bf16.f32 "
                 "{%0,%1,%2,%3}, {%4,%5,%6,%7}, {%8,%9}, {%0,%1,%2,%3};"
                 : "+f"(c[0]), "+f"(c[1]), "+f"(c[2]), "+f"(c[3])
                 : "r"(a[0]), "r"(a[1]), "r"(a[2]), "r"(a[3]), "r"(b0), "r"(b1));
}

// packed key = (bits(score + 512) & ~0xFF) | li, li = chunk*8 + ni*2 + h
__device__ __forceinline__ float key_s(uint32_t key) {
    return __uint_as_float(key & 0xFFFFFF00u) - 512.f;
}
__device__ __forceinline__ int key_kk(uint32_t key, int L) {
    int li = (int)(key & 0xFFu);
    return ((li >> 3) << 5) + ((li >> 1) & 3) * 8 + (L & 3) * 2 + (li & 1);
}

__global__ void __launch_bounds__(HT, 1)
vq_hmma_kernel(const float* __restrict__ x, float* __restrict__ out) {
    extern __shared__ char smem[];
    uint32_t sb = smem_u32(smem);
    float* ens  = (float*)(smem + SMH_ENS);
    float* e512 = (float*)(smem + SMH_ENS512);
    int*   bidx = (int*)(smem + SMH_BIDX);
    int tid = threadIdx.x, w = tid >> 5, L = tid & 31;
    int m0 = blockIdx.x * H_MBLK;

    // preload B chunk 0 first (overlaps with A register fill)
    {
        const char* ebase = (const char*)g_etb;
        for (int u = tid; u < 1024; u += HT)
            cp16(sb + SMH_B + (u >> 5) * H_RSTRIDE + (u & 31) * 16,
                 ebase + (size_t)(u >> 5) * 512 + (u & 31) * 16);
        CP_COMMIT();
    }
    for (int i = tid; i < KCODES; i += HT) {
        float e = g_enorm2[i];
        ens[i]  = e;
        e512[i] = e + 512.f;
    }

    // A fragments resident in registers: 16 ks x 4 regs (fp32 gmem -> bf16)
    uint32_t a[16][4];
    {
        const float* xb = x + (size_t)(m0 + w * 16 + (L >> 2)) * DIMS + (L & 3) * 2;
#pragma unroll
        for (int ks = 0; ks < 16; ks++)
#pragma unroll
            for (int j = 0; j < 4; j++) {
                float2 v = *(const float2*)(xb + (size_t)((j & 1) * 8) * DIMS
                                            + ks * 16 + (j >> 1) * 8);
                a[ks][j] = pack_bf2(v.x, v.y);
            }
    }

    // B ldsm lane address: n-rows (L&7)+((L>>4)<<3), k-half (L>>3)&1
    uint32_t b_lane = (uint32_t)((L & 7) + ((L >> 4) << 3)) * H_RSTRIDE
                    + (uint32_t)((L >> 3) & 1) * 16;

    // branchless packed-key top-3 (ascending) for 2 rows: w*16 + (L>>2) + {0,8}
    uint32_t m1[2], m2[2], m3[2];
#pragma unroll
    for (int q = 0; q < 2; q++) { m1[q] = ~0u; m2[q] = ~0u; m3[q] = ~0u; }

#define UPDP(ri, e_, li_, vv) do {                                              \
    float s_ = fmaf(-2.f, (vv), (e_));                                          \
    uint32_t key_ = (__float_as_uint(s_) & 0xFFFFFF00u) | (uint32_t)(li_);      \
    uint32_t lo1_ = umin(m1[ri], key_);                                         \
    uint32_t hi1_ = umax(m1[ri], key_); m1[ri] = lo1_;                          \
    uint32_t lo2_ = umin(m2[ri], hi1_);                                         \
    uint32_t hi2_ = umax(m2[ri], hi1_); m2[ri] = lo2_;                          \
    m3[ri] = umin(m3[ri], hi2_);                                                \
} while (0)

    for (int i = 0; i < H_NCHUNKS; i++) {
        CP_WAIT0();
        __syncthreads();                       // chunk i visible; frees other buf
        if (i + 1 < H_NCHUNKS) {
            const char* ebase = (const char*)g_etb + (size_t)(i + 1) * H_NCH * 512;
            uint32_t bdst = sb + SMH_B + ((i + 1) & 1) * H_BUFSZ;
            for (int u = tid; u < 1024; u += HT)
                cp16(bdst + (u >> 5) * H_RSTRIDE + (u & 31) * 16,
                     ebase + (size_t)(u >> 5) * 512 + (u & 31) * 16);
            CP_COMMIT();
        }

        uint32_t bbase = sb + SMH_B + (i & 1) * H_BUFSZ + b_lane;

        float acc[4][4];                       // 4 n-tiles x 4
#pragma unroll
        for (int ni = 0; ni < 4; ni++)
#pragma unroll
            for (int c = 0; c < 4; c++) acc[ni][c] = 0.f;

#pragma unroll
        for (int ks = 0; ks < 16; ks++) {
            uint32_t bf0[4], bf1[4];
            ldsm4(bf0, bbase + ks * 32);
            ldsm4(bf1, bbase + 16 * H_RSTRIDE + ks * 32);
            mma16816(acc[0], a[ks], bf0[0], bf0[1]);
            mma16816(acc[1], a[ks], bf0[2], bf0[3]);
            mma16816(acc[2], a[ks], bf1[0], bf1[1]);
            mma16816(acc[3], a[ks], bf1[2], bf1[3]);
        }

        int kb = i * H_NCH + (L & 3) * 2;
#pragma unroll
        for (int ni = 0; ni < 4; ni++) {
            float2 e2 = *(const float2*)(e512 + kb + ni * 8);
            int li = i * 8 + ni * 2;
            UPDP(0, e2.x, li,     acc[ni][0]); UPDP(0, e2.y, li + 1, acc[ni][1]);
            UPDP(1, e2.x, li,     acc[ni][2]); UPDP(1, e2.y, li + 1, acc[ni][3]);
        }
    }
#undef UPDP
    __syncthreads();

    // ---- decision: decode -> quad merge -> margin -> rescore -> tie vote ----
#pragma unroll 1
    for (int ri = 0; ri < 2; ri++) {
        float hv1 = key_s(m1[ri]), hv2 = key_s(m2[ri]), hv3 = key_s(m3[ri]);
        int   hk1 = key_kk(m1[ri], L), hk2 = key_kk(m2[ri], L),
              hk3 = key_kk(m3[ri], L);
        int gr = w * 16 + ri * 8 + (L >> 2);

        float v1 = hv1, v2 = hv2;
        int   k1 = hk1, k2 = hk2;
#pragma unroll
        for (int off = 1; off <= 2; off <<= 1) {
            float ov1 = __shfl_xor_sync(0xffffffffu, v1, off);
            int   ok1 = __shfl_xor_sync(0xffffffffu, k1, off);
            float ov2 = __shfl_xor_sync(0xffffffffu, v2, off);
            int   ok2 = __shfl_xor_sync(0xffffffffu, k2, off);
            merge_top2(v1, k1, v2, k2, ov1, ok1, ov2, ok2);
        }
        int widx = k1;
        bool need = (v2 - v1 < MARGIN);
        if (__any_sync(0xffffffffu, need)) {
            float ev1 = FLT_MAX, ev2 = FLT_MAX;
            int   ek1 = 0x7fffffff, ek2 = 0x7fffffff;
            if (need) {
                float lim = v1 + MARGIN;
                const float4* xr = (const float4*)(x + (size_t)(m0 + gr) * DIMS);
                float cv[3] = { hv1, hv2, hv3 };
                int   ck[3] = { hk1, hk2, hk3 };
#pragma unroll
                for (int c = 0; c < 3; c++) {
                    if (cv[c] <= lim) {
                        int kc = ck[c];
                        float s = exact_score(xr, kc, ens[kc]);
                        if (s < ev1 || (s == ev1 && kc < ek1)) {
                            ev2 = ev1; ek2 = ek1; ev1 = s; ek1 = kc;
                        } else if (s < ev2 || (s == ev2 && kc < ek2)) {
                            ev2 = s; ek2 = kc;
                        }
                    }
                }
            }
#pragma unroll
            for (int off = 1; off <= 2; off <<= 1) {
                float ov1 = __shfl_xor_sync(0xffffffffu, ev1, off);
                int   ok1 = __shfl_xor_sync(0xffffffffu, ek1, off);
                float ov2 = __shfl_xor_sync(0xffffffffu, ev2, off);
                int   ok2 = __shfl_xor_sync(0xffffffffu, ek2, off);
                merge_top2(ev1, ek1, ev2, ek2, ov1, ok1, ov2, ok2);
            }
            if (need) {
                widx = ek1;
                if (ek2 != 0x7fffffff && ev2 - ev1 < 3e-4f && (L & 3) == 0) {
                    int ka = min(ek1, ek2), kb = max(ek1, ek2);
                    widx = vote_tie(x, m0 + gr, ka, kb);
                }
            }
        }
        if ((L & 3) == 0) bidx[gr] = widx;
    }
    __syncthreads();

    // epilogue: out = x + (q - x), loss  (512 threads: 2 rows per step)
    float lsum = 0.f;
    int d = tid & 255;
    for (int m = tid >> 8; m < H_MBLK; m += 2) {
        int idx = bidx[m];
        float q  = g_eT[(size_t)idx * DIMS + d];
        float xv = x[(size_t)(m0 + m) * DIMS + d];
        out[(size_t)(m0 + m) * DIMS + d] = __fadd_rn(xv, __fsub_rn(q, xv));
        float dq = __fsub_rn(q, xv);
        lsum = fmaf(dq, dq, lsum);
    }
#pragma unroll
    for (int off = 16; off; off >>= 1)
        lsum += __shfl_xor_sync(0xffffffffu, lsum, off);
    __shared__ float wsum[16];
    if (L == 0) wsum[w] = lsum;
    __syncthreads();
    if (tid == 0) {
        float t = 0.f;
#pragma unroll
        for (int q = 0; q < 16; q++) t += wsum[q];
        atomicAdd(&g_loss, (double)t);
    }
}

__global__ void finalize_kernel(float* __restrict__ out, long long loss_index) {
    if (threadIdx.x == 0) {
        float m = (float)(g_loss / (double)((long long)N_VEC * DIMS));
        out[loss_index] = __fadd_rn(__fmul_rn(0.25f, m), m);
    }
}

// ---------------------------------------------------------------------------
extern "C" void kernel_launch(void* const* d_in, const int* in_sizes, int n_in,
                              void* d_out, int out_size) {
    const float* x   = (const float*)d_in[0];
    const float* emb = (const float*)d_in[1];
    float* out = (float*)d_out;

    dim3 tb(32, 8);
    transpose_e_kernel<<<dim3(KCODES / 32, DIMS / 32), tb>>>(emb);
    enorm_kernel<<<KCODES / 8, 256>>>();
    convert_etb_kernel<<<128, 256>>>();

    cudaFuncSetAttribute(vq_hmma_kernel,
                         cudaFuncAttributeMaxDynamicSharedMemorySize, SMH_TOTAL);
    vq_hmma_kernel<<<N_VEC / H_MBLK, HT, SMH_TOTAL>>>(x, out);

    finalize_kernel<<<1, 32>>>(out, (long long)out_size - 1);
}